// round 11
// baseline (speedup 1.0000x reference)
#include <cuda_runtime.h>
#include <math.h>

#define BB 256
#define NN 2048
#define NSUM 22   // M(6 sym), C(9), mw(3), yw(3), wsum(1)

// scratch (no allocations allowed)
__device__ float g_sq[BB];
__device__ unsigned int g_ctr;   // zero-init; monotonic across graph replays

// ---------------------------------------------------------------------------
// Pose solve for one batch from its 22 sums. fp32, tangent-form Jacobi,
// robust U construction (no division by smallest singular value).
// ---------------------------------------------------------------------------
__device__ void solve_pose(const float* __restrict__ s,
                           const float* __restrict__ tsv_in,
                           float* __restrict__ ob)
{
    float inv_ws = __fdividef(1.f, s[21]);
    float mw[3] = {s[15], s[16], s[17]};
    float yw[3] = {s[18], s[19], s[20]};

    // H = C^T - yw mw^T / ws (C[i][j] = s[6+3i+j], i=m idx, j=y idx)
    float H[3][3];
#pragma unroll
    for (int i = 0; i < 3; i++)
#pragma unroll
        for (int j = 0; j < 3; j++)
            H[i][j] = s[6 + 3 * j + i] - yw[i] * mw[j] * inv_ws;

    float mum[3], muy[3];
#pragma unroll
    for (int i = 0; i < 3; i++) { mum[i] = mw[i] * inv_ws; muy[i] = yw[i] * inv_ws; }

    // A = H^T H (symmetric)
    float A[3][3];
#pragma unroll
    for (int i = 0; i < 3; i++)
#pragma unroll
        for (int j = 0; j < 3; j++) {
            float tv = 0.f;
#pragma unroll
            for (int k = 0; k < 3; k++) tv += H[k][i] * H[k][j];
            A[i][j] = tv;
        }

    // Jacobi eigendecomposition: A = V L V^T (tangent form, fast divides)
    float V[3][3] = {{1,0,0},{0,1,0},{0,0,1}};
    for (int sweep = 0; sweep < 5; sweep++) {
#pragma unroll
        for (int r = 0; r < 3; r++) {
            int p = (r == 2) ? 1 : 0;
            int q = (r == 0) ? 1 : 2;
            float apq = A[p][q];
            float app = A[p][p], aqq = A[q][q];
            // apq == 0 -> tau huge -> t = 0 -> exact identity rotation
            float tau = (apq == 0.f) ? 3.4e38f : __fdividef(aqq - app, 2.f * apq);
            float t = __fdividef((tau >= 0.f) ? 1.f : -1.f,
                                 fabsf(tau) + sqrtf(1.f + tau * tau));
            float c = rsqrtf(1.f + t * t);
            float sn = t * c;
            float tau2 = __fdividef(sn, 1.f + c);
            A[p][p] = app - t * apq;
            A[q][q] = aqq + t * apq;
            A[p][q] = 0.f; A[q][p] = 0.f;
            int k = 3 - p - q;
            float akp = A[k][p], akq = A[k][q];
            A[k][p] = akp - sn * (akq + tau2 * akp);
            A[p][k] = A[k][p];
            A[k][q] = akq + sn * (akp - tau2 * akq);
            A[q][k] = A[k][q];
#pragma unroll
            for (int kk = 0; kk < 3; kk++) {
                float vkp = V[kk][p], vkq = V[kk][q];
                V[kk][p] = vkp - sn * (vkq + tau2 * vkp);
                V[kk][q] = vkq + sn * (vkp - tau2 * vkq);
            }
        }
    }

    // sort eigenvalues descending (columns of V follow)
    float lam[3] = {A[0][0], A[1][1], A[2][2]};
#pragma unroll
    for (int i = 0; i < 2; i++)
#pragma unroll
        for (int j = 0; j < 2 - i; j++) {
            if (lam[j] < lam[j + 1]) {
                float tl = lam[j]; lam[j] = lam[j + 1]; lam[j + 1] = tl;
#pragma unroll
                for (int k = 0; k < 3; k++) {
                    float tv = V[k][j]; V[k][j] = V[k][j + 1]; V[k][j + 1] = tv;
                }
            }
        }

    // det(V) = +1
    float detV = V[0][0] * (V[1][1] * V[2][2] - V[1][2] * V[2][1])
               - V[0][1] * (V[1][0] * V[2][2] - V[1][2] * V[2][0])
               + V[0][2] * (V[1][0] * V[2][1] - V[1][1] * V[2][0]);
    float flip = (detV < 0.f) ? -1.f : 1.f;
    V[0][2] *= flip; V[1][2] *= flip; V[2][2] *= flip;

    // u0 = normalize(H v0); u1 = normalize((H v1) perp u0); u2 = u0 x u1
    float u0[3], u1[3], u2[3];
    {
        float t0[3], t1[3];
#pragma unroll
        for (int i = 0; i < 3; i++) {
            t0[i] = H[i][0] * V[0][0] + H[i][1] * V[1][0] + H[i][2] * V[2][0];
            t1[i] = H[i][0] * V[0][1] + H[i][1] * V[1][1] + H[i][2] * V[2][1];
        }
        float n0 = rsqrtf(fmaxf(t0[0]*t0[0] + t0[1]*t0[1] + t0[2]*t0[2], 1e-30f));
#pragma unroll
        for (int i = 0; i < 3; i++) u0[i] = t0[i] * n0;
        float dot = u0[0]*t1[0] + u0[1]*t1[1] + u0[2]*t1[2];
#pragma unroll
        for (int i = 0; i < 3; i++) t1[i] -= dot * u0[i];
        float n1 = rsqrtf(fmaxf(t1[0]*t1[0] + t1[1]*t1[1] + t1[2]*t1[2], 1e-30f));
#pragma unroll
        for (int i = 0; i < 3; i++) u1[i] = t1[i] * n1;
        u2[0] = u0[1]*u1[2] - u0[2]*u1[1];
        u2[1] = u0[2]*u1[0] - u0[0]*u1[2];
        u2[2] = u0[0]*u1[1] - u0[1]*u1[0];
    }

    // R = U V^T
    float R[3][3];
#pragma unroll
    for (int i = 0; i < 3; i++) {
        float ui0 = u0[i], ui1 = u1[i], ui2 = u2[i];
#pragma unroll
        for (int j = 0; j < 3; j++)
            R[i][j] = ui0 * V[j][0] + ui1 * V[j][1] + ui2 * V[j][2];
    }

    float tt[3];
#pragma unroll
    for (int i = 0; i < 3; i++)
        tt[i] = R[i][0] * mum[0] + R[i][1] * mum[1] + R[i][2] * mum[2] - muy[i];

    float T[4][4];
#pragma unroll
    for (int i = 0; i < 3; i++) {
#pragma unroll
        for (int j = 0; j < 3; j++) T[i][j] = R[i][j];
        T[i][3] = -tt[i];
    }
    T[3][0] = 0.f; T[3][1] = 0.f; T[3][2] = 0.f; T[3][3] = 1.f;

    float Tsv[4][4];
#pragma unroll
    for (int i = 0; i < 4; i++)
#pragma unroll
        for (int j = 0; j < 4; j++) Tsv[i][j] = tsv_in[i * 4 + j];

    float Tinv[4][4];
#pragma unroll
    for (int i = 0; i < 3; i++) {
#pragma unroll
        for (int j = 0; j < 3; j++) Tinv[i][j] = Tsv[j][i];
        Tinv[i][3] = -(Tsv[0][i] * Tsv[0][3] + Tsv[1][i] * Tsv[1][3] + Tsv[2][i] * Tsv[2][3]);
    }
    Tinv[3][0] = 0.f; Tinv[3][1] = 0.f; Tinv[3][2] = 0.f; Tinv[3][3] = 1.f;

    float M1[4][4];
#pragma unroll
    for (int i = 0; i < 4; i++)
#pragma unroll
        for (int j = 0; j < 4; j++) {
            float tv = 0.f;
#pragma unroll
            for (int k = 0; k < 4; k++) tv += Tinv[i][k] * T[k][j];
            M1[i][j] = tv;
        }
#pragma unroll
    for (int i = 0; i < 4; i++)
#pragma unroll
        for (int j = 0; j < 4; j++) {
            float tv = 0.f;
#pragma unroll
            for (int k = 0; k < 4; k++) tv += M1[i][k] * Tsv[k][j];
            ob[i * 4 + j] = tv;
        }
}

// ---------------------------------------------------------------------------
__device__ __forceinline__ int sym6(int a, int c) {
    if (a > c) { int t = a; a = c; c = t; }
    return (a == 0) ? c : (a == 1) ? (2 + c) : 5;
}

__device__ __forceinline__ float q_entry(const float* __restrict__ ss, int e)
{
    int i = e / 13, j = e % 13;
    float val = 0.f;
    if (i == 0 && j == 0) {
        val = 0.f;
    } else if (i == 0 && j <= 9) {
        val = -ss[6 + (j - 1)];
    } else if (i == 0) {
        val = ss[18 + (j - 10)];
    } else if (j == 0 && i <= 9) {
        val = -ss[6 + (i - 1)];
    } else if (j == 0) {
        val = ss[18 + (i - 10)];
    } else if (i <= 9 && j <= 9) {
        int a = (i - 1) / 3, r = (i - 1) % 3;
        int bb2 = (j - 1) / 3, c = (j - 1) % 3;
        if (r == c) val = ss[sym6(a, bb2)];
    } else if (i <= 9) {
        int a = (i - 1) / 3, r = (i - 1) % 3, c = j - 10;
        if (r == c) val = -ss[15 + a];
    } else if (j <= 9) {
        int a = (j - 1) / 3, r = (j - 1) % 3, c = i - 10;
        if (r == c) val = -ss[15 + a];
    } else {
        if (i == j) val = ss[21];
    }
    return val;
}

// ---------------------------------------------------------------------------
// SINGLE fused kernel. 256 blocks x 512 threads, __launch_bounds__(512,2):
// reg cap 64/thread -> 2 blocks/SM guaranteed -> 296 slots >= 256 blocks all
// co-resident in wave 1 -> grid-wide ticket-spin cannot deadlock.
//
// Each thread loads exactly ONE float4 from each of 7 arrays (front-batched,
// 28 regs) -> ~28 warps/SM each holding 7 outstanding LDG.128.
// ---------------------------------------------------------------------------
__global__ __launch_bounds__(512, 2) void fused_all(
    const float* __restrict__ src, const float* __restrict__ trg,
    const float* __restrict__ w, const float* __restrict__ tsv,
    float* __restrict__ tout, float* __restrict__ qout)
{
    int b = blockIdx.x;
    const int NV = NN / 4;  // 512 float4 per row; 512 threads -> 1 each
    const float4* m0 = (const float4*)(src + (size_t)b * 4 * NN);
    const float4* m1 = m0 + NV;
    const float4* m2 = m0 + 2 * NV;
    const float4* y0 = (const float4*)(trg + (size_t)b * 4 * NN);
    const float4* y1 = y0 + NV;
    const float4* y2 = y0 + 2 * NV;
    const float4* wp = (const float4*)(w + (size_t)b * NN);

    int n = threadIdx.x;

    // ---- front-batched loads: 7 LDG.128 in flight per thread ----
    float4 wv4 = __ldg(wp + n);
    float4 a04 = __ldg(m0 + n), a14 = __ldg(m1 + n), a24 = __ldg(m2 + n);
    float4 c04 = __ldg(y0 + n), c14 = __ldg(y1 + n), c24 = __ldg(y2 + n);

    float acc[NSUM];
#pragma unroll
    for (int k = 0; k < NSUM; k++) acc[k] = 0.f;
    {
        const float* wvp = &wv4.x;
        const float* a0p = &a04.x; const float* a1p = &a14.x; const float* a2p = &a24.x;
        const float* c0p = &c04.x; const float* c1p = &c14.x; const float* c2p = &c24.x;
#pragma unroll
        for (int l = 0; l < 4; l++) {
            float wv = wvp[l];
            float a0 = a0p[l], a1 = a1p[l], a2 = a2p[l];
            float c0 = c0p[l], c1 = c1p[l], c2 = c2p[l];
            float w0 = wv * a0, w1 = wv * a1, w2 = wv * a2;
            acc[0]  += w0 * a0; acc[1]  += w0 * a1; acc[2]  += w0 * a2;
            acc[3]  += w1 * a1; acc[4]  += w1 * a2; acc[5]  += w2 * a2;
            acc[6]  += w0 * c0; acc[7]  += w0 * c1; acc[8]  += w0 * c2;
            acc[9]  += w1 * c0; acc[10] += w1 * c1; acc[11] += w1 * c2;
            acc[12] += w2 * c0; acc[13] += w2 * c1; acc[14] += w2 * c2;
            acc[15] += w0;      acc[16] += w1;      acc[17] += w2;
            acc[18] += wv * c0; acc[19] += wv * c1; acc[20] += wv * c2;
            acc[21] += wv;
        }
    }

    // warp reduce all 22
#pragma unroll
    for (int k = 0; k < NSUM; k++)
#pragma unroll
        for (int off = 16; off > 0; off >>= 1)
            acc[k] += __shfl_xor_sync(0xFFFFFFFFu, acc[k], off);

    __shared__ float sm[16][NSUM];
    __shared__ float sfin[NSUM];
    int wid = threadIdx.x >> 5, lane = threadIdx.x & 31;
    if (lane == 0)
#pragma unroll
        for (int k = 0; k < NSUM; k++) sm[wid][k] = acc[k];
    __syncthreads();
    if (threadIdx.x < NSUM) {
        float s = 0.f;
#pragma unroll
        for (int ww = 0; ww < 16; ww++) s += sm[ww][threadIdx.x];
        sfin[threadIdx.x] = s;
    }
    __syncthreads();

    // ---- pose (warp 12, lane 0) — overlaps everything below ----
    if (threadIdx.x == 384) {
        solve_pose(sfin, tsv, tout + b * 16);
    }

    // ---- publish norm partial + grid-wide ticket sync (warp 0) ----
    if (wid == 0) {
        unsigned int ticket = 0;
        if (lane == 0) {
            const float* s = sfin;
            float nq = 3.f * (s[0]*s[0] + s[3]*s[3] + s[5]*s[5])
                     + 6.f * (s[1]*s[1] + s[2]*s[2] + s[4]*s[4]);
#pragma unroll
            for (int k = 6; k < 15; k++) nq += 2.f * s[k] * s[k];
#pragma unroll
            for (int k = 15; k < 18; k++) nq += 6.f * s[k] * s[k];
#pragma unroll
            for (int k = 18; k < 21; k++) nq += 2.f * s[k] * s[k];
            nq += 3.f * s[21] * s[21];
            g_sq[b] = nq;
            __threadfence();
            ticket = atomicAdd(&g_ctr, 1u);
        }
        ticket = __shfl_sync(0xFFFFFFFFu, ticket, 0);
        unsigned int target = ((ticket >> 8) + 1u) << 8;   // next multiple of 256
        while (*((volatile unsigned int*)&g_ctr) < target) { }
        __threadfence();
    }

    // ---- warps 0-5 (192 threads): norm + scaled Q fill ----
    if (threadIdx.x < 192) {
        asm volatile("bar.sync 1, 192;" ::: "memory");

        // per-warp deterministic inv_scale (identical in every warp/block)
        float v = 0.f;
#pragma unroll
        for (int i = 0; i < 8; i++)
            v += __ldcg(&g_sq[lane + 32 * i]);
#pragma unroll
        for (int off = 16; off > 0; off >>= 1)
            v += __shfl_xor_sync(0xFFFFFFFFu, v, off);
        float x = rsqrtf(v);
        x = x * (1.5f - 0.5f * v * x * x);  // Newton refine

        if (threadIdx.x < 169)
            qout[b * 169 + threadIdx.x] = q_entry(sfin, threadIdx.x) * x;
    }
}

// ---------------------------------------------------------------------------
extern "C" void kernel_launch(void* const* d_in, const int* in_sizes, int n_in,
                              void* d_out, int out_size)
{
    const float* src = (const float*)d_in[0];
    const float* trg = (const float*)d_in[1];
    const float* w   = (const float*)d_in[2];
    const float* tsv = (const float*)d_in[3];
    float* out  = (float*)d_out;
    float* tout = out;                 // (B,4,4) = 4096 floats
    float* qout = out + BB * 16;       // (B,13,13) = 43264 floats

    fused_all<<<BB, 512>>>(src, trg, w, tsv, tout, qout);
}

// round 12
// speedup vs baseline: 1.0129x; 1.0129x over previous
#include <cuda_runtime.h>
#include <math.h>
#include <stdint.h>

#define BB 256
#define NN 2048
#define NSUM 22   // M(6 sym), C(9), mw(3), yw(3), wsum(1)

#define ROW_BYTES 8192                  // 2048 floats
#define TILE_BYTES (7 * ROW_BYTES)      // 57344: w, m0..m2, y0..y2

// scratch (no allocations allowed)
__device__ float g_sq[BB];
__device__ unsigned int g_ctr;   // zero-init; monotonic across graph replays

// ---------------------------------------------------------------------------
// Pose solve for one batch from its 22 sums. fp32, tangent-form Jacobi,
// robust U construction (no division by smallest singular value).
// ---------------------------------------------------------------------------
__device__ void solve_pose(const float* __restrict__ s,
                           const float* __restrict__ tsv_in,
                           float* __restrict__ ob)
{
    float inv_ws = __fdividef(1.f, s[21]);
    float mw[3] = {s[15], s[16], s[17]};
    float yw[3] = {s[18], s[19], s[20]};

    // H = C^T - yw mw^T / ws (C[i][j] = s[6+3i+j], i=m idx, j=y idx)
    float H[3][3];
#pragma unroll
    for (int i = 0; i < 3; i++)
#pragma unroll
        for (int j = 0; j < 3; j++)
            H[i][j] = s[6 + 3 * j + i] - yw[i] * mw[j] * inv_ws;

    float mum[3], muy[3];
#pragma unroll
    for (int i = 0; i < 3; i++) { mum[i] = mw[i] * inv_ws; muy[i] = yw[i] * inv_ws; }

    // A = H^T H (symmetric)
    float A[3][3];
#pragma unroll
    for (int i = 0; i < 3; i++)
#pragma unroll
        for (int j = 0; j < 3; j++) {
            float tv = 0.f;
#pragma unroll
            for (int k = 0; k < 3; k++) tv += H[k][i] * H[k][j];
            A[i][j] = tv;
        }

    // Jacobi eigendecomposition: A = V L V^T (tangent form, fast divides)
    float V[3][3] = {{1,0,0},{0,1,0},{0,0,1}};
    for (int sweep = 0; sweep < 5; sweep++) {
#pragma unroll
        for (int r = 0; r < 3; r++) {
            int p = (r == 2) ? 1 : 0;
            int q = (r == 0) ? 1 : 2;
            float apq = A[p][q];
            float app = A[p][p], aqq = A[q][q];
            // apq == 0 -> tau huge -> t = 0 -> exact identity rotation
            float tau = (apq == 0.f) ? 3.4e38f : __fdividef(aqq - app, 2.f * apq);
            float t = __fdividef((tau >= 0.f) ? 1.f : -1.f,
                                 fabsf(tau) + sqrtf(1.f + tau * tau));
            float c = rsqrtf(1.f + t * t);
            float sn = t * c;
            float tau2 = __fdividef(sn, 1.f + c);
            A[p][p] = app - t * apq;
            A[q][q] = aqq + t * apq;
            A[p][q] = 0.f; A[q][p] = 0.f;
            int k = 3 - p - q;
            float akp = A[k][p], akq = A[k][q];
            A[k][p] = akp - sn * (akq + tau2 * akp);
            A[p][k] = A[k][p];
            A[k][q] = akq + sn * (akp - tau2 * akq);
            A[q][k] = A[k][q];
#pragma unroll
            for (int kk = 0; kk < 3; kk++) {
                float vkp = V[kk][p], vkq = V[kk][q];
                V[kk][p] = vkp - sn * (vkq + tau2 * vkp);
                V[kk][q] = vkq + sn * (vkp - tau2 * vkq);
            }
        }
    }

    // sort eigenvalues descending (columns of V follow)
    float lam[3] = {A[0][0], A[1][1], A[2][2]};
#pragma unroll
    for (int i = 0; i < 2; i++)
#pragma unroll
        for (int j = 0; j < 2 - i; j++) {
            if (lam[j] < lam[j + 1]) {
                float tl = lam[j]; lam[j] = lam[j + 1]; lam[j + 1] = tl;
#pragma unroll
                for (int k = 0; k < 3; k++) {
                    float tv = V[k][j]; V[k][j] = V[k][j + 1]; V[k][j + 1] = tv;
                }
            }
        }

    // det(V) = +1
    float detV = V[0][0] * (V[1][1] * V[2][2] - V[1][2] * V[2][1])
               - V[0][1] * (V[1][0] * V[2][2] - V[1][2] * V[2][0])
               + V[0][2] * (V[1][0] * V[2][1] - V[1][1] * V[2][0]);
    float flip = (detV < 0.f) ? -1.f : 1.f;
    V[0][2] *= flip; V[1][2] *= flip; V[2][2] *= flip;

    // u0 = normalize(H v0); u1 = normalize((H v1) perp u0); u2 = u0 x u1
    float u0[3], u1[3], u2[3];
    {
        float t0[3], t1[3];
#pragma unroll
        for (int i = 0; i < 3; i++) {
            t0[i] = H[i][0] * V[0][0] + H[i][1] * V[1][0] + H[i][2] * V[2][0];
            t1[i] = H[i][0] * V[0][1] + H[i][1] * V[1][1] + H[i][2] * V[2][1];
        }
        float n0 = rsqrtf(fmaxf(t0[0]*t0[0] + t0[1]*t0[1] + t0[2]*t0[2], 1e-30f));
#pragma unroll
        for (int i = 0; i < 3; i++) u0[i] = t0[i] * n0;
        float dot = u0[0]*t1[0] + u0[1]*t1[1] + u0[2]*t1[2];
#pragma unroll
        for (int i = 0; i < 3; i++) t1[i] -= dot * u0[i];
        float n1 = rsqrtf(fmaxf(t1[0]*t1[0] + t1[1]*t1[1] + t1[2]*t1[2], 1e-30f));
#pragma unroll
        for (int i = 0; i < 3; i++) u1[i] = t1[i] * n1;
        u2[0] = u0[1]*u1[2] - u0[2]*u1[1];
        u2[1] = u0[2]*u1[0] - u0[0]*u1[2];
        u2[2] = u0[0]*u1[1] - u0[1]*u1[0];
    }

    // R = U V^T
    float R[3][3];
#pragma unroll
    for (int i = 0; i < 3; i++) {
        float ui0 = u0[i], ui1 = u1[i], ui2 = u2[i];
#pragma unroll
        for (int j = 0; j < 3; j++)
            R[i][j] = ui0 * V[j][0] + ui1 * V[j][1] + ui2 * V[j][2];
    }

    float tt[3];
#pragma unroll
    for (int i = 0; i < 3; i++)
        tt[i] = R[i][0] * mum[0] + R[i][1] * mum[1] + R[i][2] * mum[2] - muy[i];

    float T[4][4];
#pragma unroll
    for (int i = 0; i < 3; i++) {
#pragma unroll
        for (int j = 0; j < 3; j++) T[i][j] = R[i][j];
        T[i][3] = -tt[i];
    }
    T[3][0] = 0.f; T[3][1] = 0.f; T[3][2] = 0.f; T[3][3] = 1.f;

    float Tsv[4][4];
#pragma unroll
    for (int i = 0; i < 4; i++)
#pragma unroll
        for (int j = 0; j < 4; j++) Tsv[i][j] = tsv_in[i * 4 + j];

    float Tinv[4][4];
#pragma unroll
    for (int i = 0; i < 3; i++) {
#pragma unroll
        for (int j = 0; j < 3; j++) Tinv[i][j] = Tsv[j][i];
        Tinv[i][3] = -(Tsv[0][i] * Tsv[0][3] + Tsv[1][i] * Tsv[1][3] + Tsv[2][i] * Tsv[2][3]);
    }
    Tinv[3][0] = 0.f; Tinv[3][1] = 0.f; Tinv[3][2] = 0.f; Tinv[3][3] = 1.f;

    float M1[4][4];
#pragma unroll
    for (int i = 0; i < 4; i++)
#pragma unroll
        for (int j = 0; j < 4; j++) {
            float tv = 0.f;
#pragma unroll
            for (int k = 0; k < 4; k++) tv += Tinv[i][k] * T[k][j];
            M1[i][j] = tv;
        }
#pragma unroll
    for (int i = 0; i < 4; i++)
#pragma unroll
        for (int j = 0; j < 4; j++) {
            float tv = 0.f;
#pragma unroll
            for (int k = 0; k < 4; k++) tv += M1[i][k] * Tsv[k][j];
            ob[i * 4 + j] = tv;
        }
}

// ---------------------------------------------------------------------------
__device__ __forceinline__ int sym6(int a, int c) {
    if (a > c) { int t = a; a = c; c = t; }
    return (a == 0) ? c : (a == 1) ? (2 + c) : 5;
}

__device__ __forceinline__ float q_entry(const float* __restrict__ ss, int e)
{
    int i = e / 13, j = e % 13;
    float val = 0.f;
    if (i == 0 && j == 0) {
        val = 0.f;
    } else if (i == 0 && j <= 9) {
        val = -ss[6 + (j - 1)];
    } else if (i == 0) {
        val = ss[18 + (j - 10)];
    } else if (j == 0 && i <= 9) {
        val = -ss[6 + (i - 1)];
    } else if (j == 0) {
        val = ss[18 + (i - 10)];
    } else if (i <= 9 && j <= 9) {
        int a = (i - 1) / 3, r = (i - 1) % 3;
        int bb2 = (j - 1) / 3, c = (j - 1) % 3;
        if (r == c) val = ss[sym6(a, bb2)];
    } else if (i <= 9) {
        int a = (i - 1) / 3, r = (i - 1) % 3, c = j - 10;
        if (r == c) val = -ss[15 + a];
    } else if (j <= 9) {
        int a = (j - 1) / 3, r = (j - 1) % 3, c = i - 10;
        if (r == c) val = -ss[15 + a];
    } else {
        if (i == j) val = ss[21];
    }
    return val;
}

// ---------------------------------------------------------------------------
// SINGLE fused kernel, bulk-async (TMA) load path.
// 256 blocks x 256 threads; dynamic smem 57.4 KB/block; __launch_bounds__(256,2)
// -> 2 blocks/SM (smem 114.7 KB <= 227 KB, regs <= 128) -> all 256 blocks
// co-resident -> grid-wide ticket-spin cannot deadlock.
//
// Loads: 7 x cp.async.bulk of 8 KB per block (one mbarrier, expect_tx=57344).
// Outstanding bytes/SM ~114 KB >> LDG MSHR capacity -> DRAM-bandwidth-bound
// instead of latency-bound.
// ---------------------------------------------------------------------------
extern __shared__ char dyn_smem[];

__global__ __launch_bounds__(256, 2) void fused_all(
    const float* __restrict__ src, const float* __restrict__ trg,
    const float* __restrict__ w, const float* __restrict__ tsv,
    float* __restrict__ tout, float* __restrict__ qout)
{
    int b = blockIdx.x;

    __shared__ uint64_t mbar;
    __shared__ float sm[8][NSUM];
    __shared__ float sfin[NSUM];

    uint32_t mbar_addr;
    asm("{ .reg .u64 t; cvta.to.shared.u64 t, %1; cvt.u32.u64 %0, t; }"
        : "=r"(mbar_addr) : "l"(&mbar));
    uint32_t smem_base;
    asm("{ .reg .u64 t; cvta.to.shared.u64 t, %1; cvt.u32.u64 %0, t; }"
        : "=r"(smem_base) : "l"(dyn_smem));

    // ---- issue bulk copies: w, m0..m2, y0..y2 (8 KB each) ----
    if (threadIdx.x == 0) {
        asm volatile("mbarrier.init.shared.b64 [%0], %1;"
                     :: "r"(mbar_addr), "r"(1) : "memory");
    }
    __syncthreads();
    if (threadIdx.x == 0) {
        asm volatile("mbarrier.arrive.expect_tx.shared.b64 _, [%0], %1;"
                     :: "r"(mbar_addr), "r"((uint32_t)TILE_BYTES) : "memory");
        const char* g_w  = (const char*)(w   + (size_t)b * NN);
        const char* g_m  = (const char*)(src + (size_t)b * 4 * NN);
        const char* g_y  = (const char*)(trg + (size_t)b * 4 * NN);
        const char* srcs[7] = { g_w,
                                g_m, g_m + ROW_BYTES, g_m + 2 * ROW_BYTES,
                                g_y, g_y + ROW_BYTES, g_y + 2 * ROW_BYTES };
#pragma unroll
        for (int i = 0; i < 7; i++) {
            asm volatile(
                "cp.async.bulk.shared::cta.global.mbarrier::complete_tx::bytes "
                "[%0], [%1], %2, [%3];"
                :: "r"(smem_base + i * ROW_BYTES), "l"(srcs[i]),
                   "r"((uint32_t)ROW_BYTES), "r"(mbar_addr)
                : "memory");
        }
    }
    __syncthreads();

    // ---- wait for all 57344 bytes ----
    {
        uint32_t done;
        asm volatile(
            "{\n\t"
            ".reg .pred p;\n\t"
            "mbarrier.try_wait.parity.acquire.cta.shared::cta.b64 p, [%1], 0;\n\t"
            "selp.b32 %0, 1, 0, p;\n\t"
            "}"
            : "=r"(done) : "r"(mbar_addr) : "memory");
        if (!done) {
            asm volatile(
                "{\n\t"
                ".reg .pred P1;\n\t"
                "WAIT_LOOP_%=:\n\t"
                "mbarrier.try_wait.parity.acquire.cta.shared::cta.b64 P1, [%0], 0, 0x989680;\n\t"
                "@P1 bra.uni WAIT_DONE_%=;\n\t"
                "bra.uni WAIT_LOOP_%=;\n\t"
                "WAIT_DONE_%=:\n\t"
                "}"
                :: "r"(mbar_addr) : "memory");
        }
    }

    // ---- accumulate from smem (2 float4 per array per thread) ----
    const float4* W  = (const float4*)(dyn_smem);
    const float4* M0 = (const float4*)(dyn_smem + 1 * ROW_BYTES);
    const float4* M1 = (const float4*)(dyn_smem + 2 * ROW_BYTES);
    const float4* M2 = (const float4*)(dyn_smem + 3 * ROW_BYTES);
    const float4* Y0 = (const float4*)(dyn_smem + 4 * ROW_BYTES);
    const float4* Y1 = (const float4*)(dyn_smem + 5 * ROW_BYTES);
    const float4* Y2 = (const float4*)(dyn_smem + 6 * ROW_BYTES);

    float acc[NSUM];
#pragma unroll
    for (int k = 0; k < NSUM; k++) acc[k] = 0.f;

#pragma unroll
    for (int it = 0; it < 2; it++) {
        int n = threadIdx.x + it * 256;
        float4 wv4 = W[n];
        float4 a04 = M0[n], a14 = M1[n], a24 = M2[n];
        float4 c04 = Y0[n], c14 = Y1[n], c24 = Y2[n];
        const float* wvp = &wv4.x;
        const float* a0p = &a04.x; const float* a1p = &a14.x; const float* a2p = &a24.x;
        const float* c0p = &c04.x; const float* c1p = &c14.x; const float* c2p = &c24.x;
#pragma unroll
        for (int l = 0; l < 4; l++) {
            float wv = wvp[l];
            float a0 = a0p[l], a1 = a1p[l], a2 = a2p[l];
            float c0 = c0p[l], c1 = c1p[l], c2 = c2p[l];
            float w0 = wv * a0, w1 = wv * a1, w2 = wv * a2;
            acc[0]  += w0 * a0; acc[1]  += w0 * a1; acc[2]  += w0 * a2;
            acc[3]  += w1 * a1; acc[4]  += w1 * a2; acc[5]  += w2 * a2;
            acc[6]  += w0 * c0; acc[7]  += w0 * c1; acc[8]  += w0 * c2;
            acc[9]  += w1 * c0; acc[10] += w1 * c1; acc[11] += w1 * c2;
            acc[12] += w2 * c0; acc[13] += w2 * c1; acc[14] += w2 * c2;
            acc[15] += w0;      acc[16] += w1;      acc[17] += w2;
            acc[18] += wv * c0; acc[19] += wv * c1; acc[20] += wv * c2;
            acc[21] += wv;
        }
    }

    // warp reduce all 22
#pragma unroll
    for (int k = 0; k < NSUM; k++)
#pragma unroll
        for (int off = 16; off > 0; off >>= 1)
            acc[k] += __shfl_xor_sync(0xFFFFFFFFu, acc[k], off);

    int wid = threadIdx.x >> 5, lane = threadIdx.x & 31;
    if (lane == 0)
#pragma unroll
        for (int k = 0; k < NSUM; k++) sm[wid][k] = acc[k];
    __syncthreads();
    if (threadIdx.x < NSUM) {
        float s = 0.f;
#pragma unroll
        for (int ww = 0; ww < 8; ww++) s += sm[ww][threadIdx.x];
        sfin[threadIdx.x] = s;
    }
    __syncthreads();

    // ---- pose (warp 6, lane 0) — overlaps everything below ----
    if (threadIdx.x == 192) {
        solve_pose(sfin, tsv, tout + b * 16);
    }

    // ---- publish norm partial + grid-wide ticket sync (warp 0) ----
    if (wid == 0) {
        unsigned int ticket = 0;
        if (lane == 0) {
            const float* s = sfin;
            float nq = 3.f * (s[0]*s[0] + s[3]*s[3] + s[5]*s[5])
                     + 6.f * (s[1]*s[1] + s[2]*s[2] + s[4]*s[4]);
#pragma unroll
            for (int k = 6; k < 15; k++) nq += 2.f * s[k] * s[k];
#pragma unroll
            for (int k = 15; k < 18; k++) nq += 6.f * s[k] * s[k];
#pragma unroll
            for (int k = 18; k < 21; k++) nq += 2.f * s[k] * s[k];
            nq += 3.f * s[21] * s[21];
            g_sq[b] = nq;
            __threadfence();
            ticket = atomicAdd(&g_ctr, 1u);
        }
        ticket = __shfl_sync(0xFFFFFFFFu, ticket, 0);
        unsigned int target = ((ticket >> 8) + 1u) << 8;   // next multiple of 256
        while (*((volatile unsigned int*)&g_ctr) < target) { }
        __threadfence();
    }

    // ---- warps 0-5 (192 threads): norm + scaled Q fill ----
    if (threadIdx.x < 192) {
        asm volatile("bar.sync 1, 192;" ::: "memory");

        // per-warp deterministic inv_scale (identical in every warp/block)
        float v = 0.f;
#pragma unroll
        for (int i = 0; i < 8; i++)
            v += __ldcg(&g_sq[lane + 32 * i]);
#pragma unroll
        for (int off = 16; off > 0; off >>= 1)
            v += __shfl_xor_sync(0xFFFFFFFFu, v, off);
        float x = rsqrtf(v);
        x = x * (1.5f - 0.5f * v * x * x);  // Newton refine

        if (threadIdx.x < 169)
            qout[b * 169 + threadIdx.x] = q_entry(sfin, threadIdx.x) * x;
    }
}

// ---------------------------------------------------------------------------
extern "C" void kernel_launch(void* const* d_in, const int* in_sizes, int n_in,
                              void* d_out, int out_size)
{
    const float* src = (const float*)d_in[0];
    const float* trg = (const float*)d_in[1];
    const float* w   = (const float*)d_in[2];
    const float* tsv = (const float*)d_in[3];
    float* out  = (float*)d_out;
    float* tout = out;                 // (B,4,4) = 4096 floats
    float* qout = out + BB * 16;       // (B,13,13) = 43264 floats

    cudaFuncSetAttribute(fused_all,
                         cudaFuncAttributeMaxDynamicSharedMemorySize,
                         TILE_BYTES);
    fused_all<<<BB, 256, TILE_BYTES>>>(src, trg, w, tsv, tout, qout);
}

// round 13
// speedup vs baseline: 1.2281x; 1.2125x over previous
#include <cuda_runtime.h>
#include <math.h>

#define BB 256
#define NN 2048
#define NSUM 22   // M(6 sym), C(9), mw(3), yw(3), wsum(1)

// scratch (no allocations allowed)
__device__ float g_sq[BB];
__device__ unsigned int g_ctr;   // zero-init; monotonic across graph replays

// ---------------------------------------------------------------------------
// Closed-form eigenvector for symmetric A at eigenvalue lam: null-vector of
// (A - lam I) via best-of-3 row cross-products (all computable in parallel).
// Returns UNnormalized vector.
// ---------------------------------------------------------------------------
__device__ __forceinline__ void eigvec_raw(const float A[3][3], float lam,
                                           float out[3])
{
    float b00 = A[0][0] - lam, b11 = A[1][1] - lam, b22 = A[2][2] - lam;
    float b01 = A[0][1], b02 = A[0][2], b12 = A[1][2];
    // rows: r0=(b00,b01,b02) r1=(b01,b11,b12) r2=(b02,b12,b22)
    float c0[3] = { b01 * b12 - b02 * b11,   // r0 x r1
                    b02 * b01 - b00 * b12,
                    b00 * b11 - b01 * b01 };
    float c1[3] = { b01 * b22 - b02 * b12,   // r0 x r2
                    b02 * b02 - b00 * b22,
                    b00 * b12 - b02 * b01 };
    float c2[3] = { b11 * b22 - b12 * b12,   // r1 x r2
                    b12 * b02 - b01 * b22,
                    b01 * b12 - b11 * b02 };
    float n0 = c0[0]*c0[0] + c0[1]*c0[1] + c0[2]*c0[2];
    float n1 = c1[0]*c1[0] + c1[1]*c1[1] + c1[2]*c1[2];
    float n2 = c2[0]*c2[0] + c2[1]*c2[1] + c2[2]*c2[2];
    const float* best = c0;
    float nb = n0;
    if (n1 > nb) { best = c1; nb = n1; }
    if (n2 > nb) { best = c2; }
    out[0] = best[0]; out[1] = best[1]; out[2] = best[2];
}

// ---------------------------------------------------------------------------
// Pose solve: closed-form (Cardano) 3x3 symmetric eigensolve — short serial
// chain (~550 cyc) instead of iterative Jacobi (~2200 cyc).
// ---------------------------------------------------------------------------
__device__ void solve_pose(const float* __restrict__ s,
                           const float* __restrict__ tsv_in,
                           float* __restrict__ ob)
{
    float inv_ws = __fdividef(1.f, s[21]);
    float mw[3] = {s[15], s[16], s[17]};
    float yw[3] = {s[18], s[19], s[20]};

    // H = C^T - yw mw^T / ws (C[i][j] = s[6+3i+j], i=m idx, j=y idx)
    float H[3][3];
#pragma unroll
    for (int i = 0; i < 3; i++)
#pragma unroll
        for (int j = 0; j < 3; j++)
            H[i][j] = s[6 + 3 * j + i] - yw[i] * mw[j] * inv_ws;

    float mum[3], muy[3];
#pragma unroll
    for (int i = 0; i < 3; i++) { mum[i] = mw[i] * inv_ws; muy[i] = yw[i] * inv_ws; }

    // A = H^T H (symmetric)
    float A[3][3];
#pragma unroll
    for (int i = 0; i < 3; i++)
#pragma unroll
        for (int j = 0; j < 3; j++) {
            float tv = 0.f;
#pragma unroll
            for (int k = 0; k < 3; k++) tv += H[k][i] * H[k][j];
            A[i][j] = tv;
        }

    // ---- Cardano eigenvalues of A ----
    float m = (A[0][0] + A[1][1] + A[2][2]) * (1.f / 3.f);
    float K00 = A[0][0] - m, K11 = A[1][1] - m, K22 = A[2][2] - m;
    float a01 = A[0][1], a02 = A[0][2], a12 = A[1][2];
    float p2 = (K00*K00 + K11*K11 + K22*K22) * (1.f / 6.f)
             + (a01*a01 + a02*a02 + a12*a12) * (1.f / 3.f);
    float p = sqrtf(fmaxf(p2, 1e-30f));
    float detK = K00 * (K11 * K22 - a12 * a12)
               - a01 * (a01 * K22 - a12 * a02)
               + a02 * (a01 * a12 - K11 * a02);
    float r = __fdividef(detK, 2.f * p * fmaxf(p2, 1e-30f));
    r = fminf(fmaxf(r, -1.f), 1.f);
    float phi = acosf(r) * (1.f / 3.f);
    float lam0   = m + 2.f * p * __cosf(phi);                  // largest
    float lammin = m + 2.f * p * __cosf(phi + 2.09439510239f); // smallest
    float lam1   = 3.f * m - lam0 - lammin;                    // middle

    // ---- eigenvectors v0 (lam0), v1 (lam1), v2 = v0 x v1 ----
    float v0[3], v1r[3];
    eigvec_raw(A, lam0, v0);
    eigvec_raw(A, lam1, v1r);
    {
        float nv0 = rsqrtf(fmaxf(v0[0]*v0[0] + v0[1]*v0[1] + v0[2]*v0[2], 1e-30f));
#pragma unroll
        for (int i = 0; i < 3; i++) v0[i] *= nv0;
        float dotv = v0[0]*v1r[0] + v0[1]*v1r[1] + v0[2]*v1r[2];
#pragma unroll
        for (int i = 0; i < 3; i++) v1r[i] -= dotv * v0[i];
        float nv1 = rsqrtf(fmaxf(v1r[0]*v1r[0] + v1r[1]*v1r[1] + v1r[2]*v1r[2], 1e-30f));
#pragma unroll
        for (int i = 0; i < 3; i++) v1r[i] *= nv1;
    }
    float v2[3] = { v0[1]*v1r[2] - v0[2]*v1r[1],
                    v0[2]*v1r[0] - v0[0]*v1r[2],
                    v0[0]*v1r[1] - v0[1]*v1r[0] };

    // ---- u0 = normalize(H v0); u1 = normalize((H v1) perp u0); u2 = u0 x u1 ----
    float u0[3], u1[3], u2[3];
    {
        float t0[3], t1[3];
#pragma unroll
        for (int i = 0; i < 3; i++) {
            t0[i] = H[i][0] * v0[0]  + H[i][1] * v0[1]  + H[i][2] * v0[2];
            t1[i] = H[i][0] * v1r[0] + H[i][1] * v1r[1] + H[i][2] * v1r[2];
        }
        float n0 = rsqrtf(fmaxf(t0[0]*t0[0] + t0[1]*t0[1] + t0[2]*t0[2], 1e-30f));
#pragma unroll
        for (int i = 0; i < 3; i++) u0[i] = t0[i] * n0;
        float dotu = u0[0]*t1[0] + u0[1]*t1[1] + u0[2]*t1[2];
#pragma unroll
        for (int i = 0; i < 3; i++) t1[i] -= dotu * u0[i];
        float n1 = rsqrtf(fmaxf(t1[0]*t1[0] + t1[1]*t1[1] + t1[2]*t1[2], 1e-30f));
#pragma unroll
        for (int i = 0; i < 3; i++) u1[i] = t1[i] * n1;
        u2[0] = u0[1]*u1[2] - u0[2]*u1[1];
        u2[1] = u0[2]*u1[0] - u0[0]*u1[2];
        u2[2] = u0[0]*u1[1] - u0[1]*u1[0];
    }

    // R = U V^T (det +1 by construction: v2 = v0 x v1, u2 = u0 x u1)
    float R[3][3];
#pragma unroll
    for (int i = 0; i < 3; i++) {
        float ui0 = u0[i], ui1 = u1[i], ui2 = u2[i];
#pragma unroll
        for (int j = 0; j < 3; j++)
            R[i][j] = ui0 * v0[j] + ui1 * v1r[j] + ui2 * v2[j];
    }

    float tt[3];
#pragma unroll
    for (int i = 0; i < 3; i++)
        tt[i] = R[i][0] * mum[0] + R[i][1] * mum[1] + R[i][2] * mum[2] - muy[i];

    float T[4][4];
#pragma unroll
    for (int i = 0; i < 3; i++) {
#pragma unroll
        for (int j = 0; j < 3; j++) T[i][j] = R[i][j];
        T[i][3] = -tt[i];
    }
    T[3][0] = 0.f; T[3][1] = 0.f; T[3][2] = 0.f; T[3][3] = 1.f;

    float Tsv[4][4];
#pragma unroll
    for (int i = 0; i < 4; i++)
#pragma unroll
        for (int j = 0; j < 4; j++) Tsv[i][j] = tsv_in[i * 4 + j];

    float Tinv[4][4];
#pragma unroll
    for (int i = 0; i < 3; i++) {
#pragma unroll
        for (int j = 0; j < 3; j++) Tinv[i][j] = Tsv[j][i];
        Tinv[i][3] = -(Tsv[0][i] * Tsv[0][3] + Tsv[1][i] * Tsv[1][3] + Tsv[2][i] * Tsv[2][3]);
    }
    Tinv[3][0] = 0.f; Tinv[3][1] = 0.f; Tinv[3][2] = 0.f; Tinv[3][3] = 1.f;

    float M1[4][4];
#pragma unroll
    for (int i = 0; i < 4; i++)
#pragma unroll
        for (int j = 0; j < 4; j++) {
            float tv = 0.f;
#pragma unroll
            for (int k = 0; k < 4; k++) tv += Tinv[i][k] * T[k][j];
            M1[i][j] = tv;
        }
#pragma unroll
    for (int i = 0; i < 4; i++)
#pragma unroll
        for (int j = 0; j < 4; j++) {
            float tv = 0.f;
#pragma unroll
            for (int k = 0; k < 4; k++) tv += M1[i][k] * Tsv[k][j];
            ob[i * 4 + j] = tv;
        }
}

// ---------------------------------------------------------------------------
__device__ __forceinline__ int sym6(int a, int c) {
    if (a > c) { int t = a; a = c; c = t; }
    return (a == 0) ? c : (a == 1) ? (2 + c) : 5;
}

__device__ __forceinline__ float q_entry(const float* __restrict__ ss, int e)
{
    int i = e / 13, j = e % 13;
    float val = 0.f;
    if (i == 0 && j == 0) {
        val = 0.f;
    } else if (i == 0 && j <= 9) {
        val = -ss[6 + (j - 1)];
    } else if (i == 0) {
        val = ss[18 + (j - 10)];
    } else if (j == 0 && i <= 9) {
        val = -ss[6 + (i - 1)];
    } else if (j == 0) {
        val = ss[18 + (i - 10)];
    } else if (i <= 9 && j <= 9) {
        int a = (i - 1) / 3, r = (i - 1) % 3;
        int bb2 = (j - 1) / 3, c = (j - 1) % 3;
        if (r == c) val = ss[sym6(a, bb2)];
    } else if (i <= 9) {
        int a = (i - 1) / 3, r = (i - 1) % 3, c = j - 10;
        if (r == c) val = -ss[15 + a];
    } else if (j <= 9) {
        int a = (j - 1) / 3, r = (j - 1) % 3, c = i - 10;
        if (r == c) val = -ss[15 + a];
    } else {
        if (i == j) val = ss[21];
    }
    return val;
}

// ---------------------------------------------------------------------------
// SINGLE fused kernel. 256 blocks x 256 threads, __launch_bounds__(256,2)
// -> 2 blocks/SM x 148 SMs = 296 slots >= 256 blocks co-resident -> the
// grid-wide ticket-spin cannot deadlock.
//
// Role split after block reduction:
//   warps 0-5 (0-191): precompute unscaled Q entry, then bar 1 (224)
//   warp 6 (192-223):  pose solve (off the barrier, overlaps tail)
//   warp 7 (224-255):  norm publish + ticket + spin + inv_scale -> smem,
//                      then bar 1 (224)
// ---------------------------------------------------------------------------
__global__ __launch_bounds__(256, 2) void fused_all(
    const float* __restrict__ src, const float* __restrict__ trg,
    const float* __restrict__ w, const float* __restrict__ tsv,
    float* __restrict__ tout, float* __restrict__ qout)
{
    int b = blockIdx.x;
    const int NV = NN / 4;  // 512 float4 per row; 256 threads -> 2 each
    const float4* m0 = (const float4*)(src + (size_t)b * 4 * NN);
    const float4* m1 = m0 + NV;
    const float4* m2 = m0 + 2 * NV;
    const float4* y0 = (const float4*)(trg + (size_t)b * 4 * NN);
    const float4* y1 = y0 + NV;
    const float4* y2 = y0 + 2 * NV;
    const float4* wp = (const float4*)(w + (size_t)b * NN);

    float acc[NSUM];
#pragma unroll
    for (int k = 0; k < NSUM; k++) acc[k] = 0.f;

#pragma unroll 2
    for (int n = threadIdx.x; n < NV; n += 256) {
        float4 wv4 = __ldg(wp + n);
        float4 a04 = __ldg(m0 + n), a14 = __ldg(m1 + n), a24 = __ldg(m2 + n);
        float4 c04 = __ldg(y0 + n), c14 = __ldg(y1 + n), c24 = __ldg(y2 + n);
        const float* wvp = &wv4.x;
        const float* a0p = &a04.x; const float* a1p = &a14.x; const float* a2p = &a24.x;
        const float* c0p = &c04.x; const float* c1p = &c14.x; const float* c2p = &c24.x;
#pragma unroll
        for (int l = 0; l < 4; l++) {
            float wv = wvp[l];
            float a0 = a0p[l], a1 = a1p[l], a2 = a2p[l];
            float c0 = c0p[l], c1 = c1p[l], c2 = c2p[l];
            float w0 = wv * a0, w1 = wv * a1, w2 = wv * a2;
            acc[0]  += w0 * a0; acc[1]  += w0 * a1; acc[2]  += w0 * a2;
            acc[3]  += w1 * a1; acc[4]  += w1 * a2; acc[5]  += w2 * a2;
            acc[6]  += w0 * c0; acc[7]  += w0 * c1; acc[8]  += w0 * c2;
            acc[9]  += w1 * c0; acc[10] += w1 * c1; acc[11] += w1 * c2;
            acc[12] += w2 * c0; acc[13] += w2 * c1; acc[14] += w2 * c2;
            acc[15] += w0;      acc[16] += w1;      acc[17] += w2;
            acc[18] += wv * c0; acc[19] += wv * c1; acc[20] += wv * c2;
            acc[21] += wv;
        }
    }

    // warp reduce all 22
#pragma unroll
    for (int k = 0; k < NSUM; k++)
#pragma unroll
        for (int off = 16; off > 0; off >>= 1)
            acc[k] += __shfl_xor_sync(0xFFFFFFFFu, acc[k], off);

    __shared__ float sm[8][NSUM];
    __shared__ float sfin[NSUM];
    __shared__ float s_inv;
    int wid = threadIdx.x >> 5, lane = threadIdx.x & 31;
    if (lane == 0)
#pragma unroll
        for (int k = 0; k < NSUM; k++) sm[wid][k] = acc[k];
    __syncthreads();
    if (threadIdx.x < NSUM) {
        float s = 0.f;
#pragma unroll
        for (int ww = 0; ww < 8; ww++) s += sm[ww][threadIdx.x];
        sfin[threadIdx.x] = s;
    }
    __syncthreads();

    if (wid == 6) {
        // ---- pose (warp 6, lane 0): short Cardano chain, off the barrier ----
        if (lane == 0) solve_pose(sfin, tsv, tout + b * 16);
    } else if (wid == 7) {
        // ---- norm publish + grid-wide ticket sync + inv_scale broadcast ----
        unsigned int ticket = 0;
        if (lane == 0) {
            const float* s = sfin;
            float nq = 3.f * (s[0]*s[0] + s[3]*s[3] + s[5]*s[5])
                     + 6.f * (s[1]*s[1] + s[2]*s[2] + s[4]*s[4]);
#pragma unroll
            for (int k = 6; k < 15; k++) nq += 2.f * s[k] * s[k];
#pragma unroll
            for (int k = 15; k < 18; k++) nq += 6.f * s[k] * s[k];
#pragma unroll
            for (int k = 18; k < 21; k++) nq += 2.f * s[k] * s[k];
            nq += 3.f * s[21] * s[21];
            g_sq[b] = nq;
            __threadfence();
            ticket = atomicAdd(&g_ctr, 1u);
            unsigned int target = ((ticket >> 8) + 1u) << 8;  // next mult of 256
            while (*((volatile unsigned int*)&g_ctr) < target) { }
        }
        __syncwarp();
        __threadfence();
        // whole warp: deterministic global norm from g_sq
        float v = __ldcg(&g_sq[lane]) + __ldcg(&g_sq[lane + 32])
                + __ldcg(&g_sq[lane + 64]) + __ldcg(&g_sq[lane + 96])
                + __ldcg(&g_sq[lane + 128]) + __ldcg(&g_sq[lane + 160])
                + __ldcg(&g_sq[lane + 192]) + __ldcg(&g_sq[lane + 224]);
#pragma unroll
        for (int off = 16; off > 0; off >>= 1)
            v += __shfl_xor_sync(0xFFFFFFFFu, v, off);
        if (lane == 0) {
            float x = rsqrtf(v);
            x = x * (1.5f - 0.5f * v * x * x);  // Newton refine
            s_inv = x;
        }
        asm volatile("bar.sync 1, 224;" ::: "memory");
    } else {
        // ---- warps 0-5: precompute unscaled Q entry, then wait for scale ----
        float val = (threadIdx.x < 169) ? q_entry(sfin, threadIdx.x) : 0.f;
        asm volatile("bar.sync 1, 224;" ::: "memory");
        if (threadIdx.x < 169)
            qout[b * 169 + threadIdx.x] = val * s_inv;
    }
}

// ---------------------------------------------------------------------------
extern "C" void kernel_launch(void* const* d_in, const int* in_sizes, int n_in,
                              void* d_out, int out_size)
{
    const float* src = (const float*)d_in[0];
    const float* trg = (const float*)d_in[1];
    const float* w   = (const float*)d_in[2];
    const float* tsv = (const float*)d_in[3];
    float* out  = (float*)d_out;
    float* tout = out;                 // (B,4,4) = 4096 floats
    float* qout = out + BB * 16;       // (B,13,13) = 43264 floats

    fused_all<<<BB, 256>>>(src, trg, w, tsv, tout, qout);
}